// round 8
// baseline (speedup 1.0000x reference)
#include <cuda_runtime.h>
#include <cuda_bf16.h>
#include <cstdint>

// Problem constants
#define B_ 4
#define C_ 96
#define H_ 64
#define W_ 64
#define HW_ 4096
#define O_ 192
#define CC_ 288   // 3*C

// ---------------- scratch (device globals; no allocation allowed) ----------------
__device__ __align__(16) float g_off3[B_*18*HW_];
__device__ __align__(16) float g_off5[B_*50*HW_];
__device__ __align__(16) float g_off7[B_*98*HW_];
__device__ __align__(16) float g_xc  [B_*CC_*HW_];
__device__ __align__(16) float g_wt3 [864*20];
__device__ __align__(16) float g_wt5 [864*52];
__device__ __align__(16) float g_wt7 [864*100];
__device__ __align__(16) float g_wpt [CC_*O_];
__device__ __align__(16) float g_betap[O_];

// ---------------- fused weight prep ----------------
// blockIdx.y in {0,1,2}: transpose offset-conv weights to [c*9+r][ocp] (zero-padded)
// blockIdx.y == 3      : transpose pointwise weights to [c][o] with BN fold + betap
__global__ void prep_all_kernel(const float* __restrict__ w3,
                                const float* __restrict__ w5,
                                const float* __restrict__ w7,
                                const float* __restrict__ w_pw,
                                const float* __restrict__ gp, const float* __restrict__ bp,
                                const float* __restrict__ mp, const float* __restrict__ vp) {
    int br = blockIdx.y;
    int i = blockIdx.x * blockDim.x + threadIdx.x;
    if (br == 3) {
        if (i < CC_ * O_) {
            int c = i / O_, o = i - c * O_;
            float inv = gp[o] * rsqrtf(vp[o] + 1e-5f);
            g_wpt[i] = w_pw[o * CC_ + c] * inv;
        }
        if (i < O_) {
            float inv = gp[i] * rsqrtf(vp[i] + 1e-5f);
            g_betap[i] = bp[i] - mp[i] * inv;
        }
        return;
    }
    const float* w = (br == 0) ? w3 : (br == 1) ? w5 : w7;
    float* wt      = (br == 0) ? g_wt3 : (br == 1) ? g_wt5 : g_wt7;
    int OC  = (br == 0) ? 18 : (br == 1) ? 50 : 98;
    int OCP = (br == 0) ? 20 : (br == 1) ? 52 : 100;
    int total = 864 * OCP;
    if (i >= total) return;
    int r = i / OCP, oc = i - r * OCP;
    wt[i] = (oc < OC) ? w[oc * 864 + r] : 0.f;
}

// ---------------- offset conv: 3x3, pad 1, C_=96 in, OC out ----------------
// block = 256 threads: 16 pixel-groups (x4 pixels) x 16 oc-groups (x4 oc)
template<int OC, int OCP, int BR>
__global__ __launch_bounds__(256) void offconv_kernel(const float* __restrict__ x,
                                                      const float* __restrict__ bias) {
    constexpr int NG  = OCP / 4;
    constexpr int GPT = (NG + 15) / 16;
    const float* wt = (BR == 0) ? g_wt3 : (BR == 1) ? g_wt5 : g_wt7;
    float* out      = (BR == 0) ? g_off3 : (BR == 1) ? g_off5 : g_off7;

    __shared__ float xs[16][3][72];
    int h = blockIdx.x, b = blockIdx.y;
    int t = threadIdx.x;
    int pg = t & 15;         // pixel group
    int og = t >> 4;         // oc group base
    int px0 = pg * 4;

    float acc[GPT][4][4];
#pragma unroll
    for (int g = 0; g < GPT; ++g)
#pragma unroll
        for (int pp = 0; pp < 4; ++pp)
#pragma unroll
            for (int o = 0; o < 4; ++o) acc[g][pp][o] = 0.f;

    const float* xb = x + b * C_ * HW_;

    for (int cc = 0; cc < C_; cc += 16) {
        // stage 16 channels x 3 rows x (W+halo) into smem
        for (int idx = t; idx < 16 * 3 * 72; idx += 256) {
            int ci = idx / 216; int rem = idx - ci * 216;
            int ky = rem / 72;  int s = rem - ky * 72;
            int xcol = s - 1;   int yrow = h - 1 + ky;
            float v = 0.f;
            if (xcol >= 0 && xcol < W_ && yrow >= 0 && yrow < H_)
                v = __ldg(xb + (cc + ci) * HW_ + yrow * W_ + xcol);
            xs[ci][ky][s] = v;
        }
        __syncthreads();

#pragma unroll 2
        for (int ci = 0; ci < 16; ++ci) {
#pragma unroll
            for (int ky = 0; ky < 3; ++ky) {
                float4 va = *(const float4*)&xs[ci][ky][px0];
                float4 vb = *(const float4*)&xs[ci][ky][px0 + 4];
                float v[6] = {va.x, va.y, va.z, va.w, vb.x, vb.y};
                const float* wr = wt + ((cc + ci) * 9 + ky * 3) * OCP;
#pragma unroll
                for (int kx = 0; kx < 3; ++kx) {
#pragma unroll
                    for (int g = 0; g < GPT; ++g) {
                        int gi = og + g * 16;
                        if (gi < NG) {
                            float4 w4 = __ldg((const float4*)(wr + kx * OCP + gi * 4));
#pragma unroll
                            for (int pp = 0; pp < 4; ++pp) {
                                float xv = v[pp + kx];
                                acc[g][pp][0] = fmaf(xv, w4.x, acc[g][pp][0]);
                                acc[g][pp][1] = fmaf(xv, w4.y, acc[g][pp][1]);
                                acc[g][pp][2] = fmaf(xv, w4.z, acc[g][pp][2]);
                                acc[g][pp][3] = fmaf(xv, w4.w, acc[g][pp][3]);
                            }
                        }
                    }
                }
            }
        }
        __syncthreads();
    }

    float* ob = out + b * OC * HW_ + h * W_;
#pragma unroll
    for (int g = 0; g < GPT; ++g) {
        int gi = og + g * 16;
        if (gi < NG) {
#pragma unroll
            for (int o = 0; o < 4; ++o) {
                int oc = gi * 4 + o;
                if (oc < OC) {
                    float bs = __ldg(bias + oc);
                    float4 st = make_float4(acc[g][0][o] + bs, acc[g][1][o] + bs,
                                            acc[g][2][o] + bs, acc[g][3][o] + bs);
                    *(float4*)&ob[oc * HW_ + px0] = st;
                }
            }
        }
    }
}

// ---------------- deformable sample + depthwise + BN + ReLU ----------------
// block = 512 threads: 64 pixels x 8 channel groups; each thread handles
// TWO channels per outer iteration (c, c+8) -> 8 independent gathers in flight.
template<int K, int BR>
__global__ __launch_bounds__(512) void deform_kernel(const float* __restrict__ x,
                                                     const float* __restrict__ wdw,
                                                     const float* __restrict__ gm,
                                                     const float* __restrict__ bt,
                                                     const float* __restrict__ mn,
                                                     const float* __restrict__ vr,
                                                     int cofs) {
    constexpr int K2 = K * K;
    constexpr int R  = (K - 1) / 2;
    const float* off = (BR == 0) ? g_off3 : (BR == 1) ? g_off5 : g_off7;

    __shared__ int    s_m[K2 * 64];
    __shared__ float2 s_w[K2 * 64];
    __shared__ float  s_dw[C_ * K2];

    int h = blockIdx.x, b = blockIdx.y;
    int t = threadIdx.x;

    // stage depthwise weights once per block (broadcast LDS thereafter)
    for (int idx = t; idx < C_ * K2; idx += 512)
        s_dw[idx] = wdw[idx];

    // stage per-(tap,pixel) metadata, shared by all channels
    for (int idx = t; idx < K2 * 64; idx += 512) {
        int j = idx >> 6, p = idx & 63;
        const float* ob = off + ((b * (2 * K2) + j) * H_ + h) * W_;
        float dy = __ldg(ob + p);
        float dx = __ldg(ob + K2 * HW_ + p);
        float py = (float)h + (float)(j / K - R) + dy;
        float px = (float)p + (float)(j % K - R) + dx;
        py = fminf(fmaxf(py, 0.f), (float)(H_ - 1));
        px = fminf(fmaxf(px, 0.f), (float)(W_ - 1));
        float fy = floorf(py), fx = floorf(px);
        int y0 = (int)fy, x0 = (int)fx;
        int xst = (x0 < W_ - 1) ? 1 : 0;
        int yst = (y0 < H_ - 1) ? 1 : 0;
        s_m[idx] = (y0 * W_ + x0) | (xst << 16) | (yst << 17);
        s_w[idx] = make_float2(py - fy, px - fx);
    }
    __syncthreads();

    int p  = t & 63;
    int cg = t >> 6;     // 0..7
    // 96 channels / (8 groups * 2 per iter) = 6 outer iterations
    for (int c0 = 0; c0 < C_; c0 += 16) {
        int ca = c0 + cg;
        int cb = ca + 8;
        const float* xpa = x + (b * C_ + ca) * HW_;
        const float* xpb = x + (b * C_ + cb) * HW_;
        const float* wra = s_dw + ca * K2;
        const float* wrb = s_dw + cb * K2;
        float acca = 0.f, accb = 0.f;

        // literal unroll pragmas: full for K<=5, 7 for K=7 (register pressure)
        if constexpr (K2 <= 25) {
#pragma unroll
            for (int j = 0; j < K2; ++j) {
                int meta = s_m[(j << 6) + p];
                float2 wv = s_w[(j << 6) + p];
                int base = meta & 0xFFFF;
                int xst  = (meta >> 16) & 1;
                int yst  = ((meta >> 17) & 1) ? W_ : 0;
                float a00 = __ldg(xpa + base);
                float a01 = __ldg(xpa + base + xst);
                float a10 = __ldg(xpa + base + yst);
                float a11 = __ldg(xpa + base + yst + xst);
                float b00 = __ldg(xpb + base);
                float b01 = __ldg(xpb + base + xst);
                float b10 = __ldg(xpb + base + yst);
                float b11 = __ldg(xpb + base + yst + xst);
                float ta = a00 + wv.y * (a01 - a00);
                float ua = a10 + wv.y * (a11 - a10);
                float sa = ta + wv.x * (ua - ta);
                float tb = b00 + wv.y * (b01 - b00);
                float ub = b10 + wv.y * (b11 - b10);
                float sb = tb + wv.x * (ub - tb);
                acca = fmaf(sa, wra[j], acca);
                accb = fmaf(sb, wrb[j], accb);
            }
        } else {
#pragma unroll 7
            for (int j = 0; j < K2; ++j) {
                int meta = s_m[(j << 6) + p];
                float2 wv = s_w[(j << 6) + p];
                int base = meta & 0xFFFF;
                int xst  = (meta >> 16) & 1;
                int yst  = ((meta >> 17) & 1) ? W_ : 0;
                float a00 = __ldg(xpa + base);
                float a01 = __ldg(xpa + base + xst);
                float a10 = __ldg(xpa + base + yst);
                float a11 = __ldg(xpa + base + yst + xst);
                float b00 = __ldg(xpb + base);
                float b01 = __ldg(xpb + base + xst);
                float b10 = __ldg(xpb + base + yst);
                float b11 = __ldg(xpb + base + yst + xst);
                float ta = a00 + wv.y * (a01 - a00);
                float ua = a10 + wv.y * (a11 - a10);
                float sa = ta + wv.x * (ua - ta);
                float tb = b00 + wv.y * (b01 - b00);
                float ub = b10 + wv.y * (b11 - b10);
                float sb = tb + wv.x * (ub - tb);
                acca = fmaf(sa, wra[j], acca);
                accb = fmaf(sb, wrb[j], accb);
            }
        }

        float inva = __ldg(gm + ca) * rsqrtf(__ldg(vr + ca) + 1e-5f);
        float invb = __ldg(gm + cb) * rsqrtf(__ldg(vr + cb) + 1e-5f);
        float oa  = fmaf(acca, inva, __ldg(bt + ca) - __ldg(mn + ca) * inva);
        float obv = fmaf(accb, invb, __ldg(bt + cb) - __ldg(mn + cb) * invb);
        g_xc[((b * CC_ + cofs + ca) * H_ + h) * W_ + p] = fmaxf(oa, 0.f);
        g_xc[((b * CC_ + cofs + cb) * H_ + h) * W_ + p] = fmaxf(obv, 0.f);
    }
}

// ---------------- pointwise GEMM (fused BN+ReLU): out[b,o,m] = relu(sum_c xc*wpt + betap) ----------------
__global__ __launch_bounds__(256) void pwgemm_kernel(float* __restrict__ out) {
    __shared__ float As[8][64];
    __shared__ float Bs[8][64];
    int b  = blockIdx.z;
    int m0 = blockIdx.x * 64;
    int n0 = blockIdx.y * 64;
    int t  = threadIdx.x;
    int tx = t & 15, ty = t >> 4;

    float acc[4][4] = {};
    const float* Ab = g_xc + b * CC_ * HW_ + m0;

    for (int k0 = 0; k0 < CC_; k0 += 8) {
        int kk = t >> 6, mm = t & 63;
        As[kk][mm]     = Ab[(k0 + kk) * HW_ + mm];
        As[kk + 4][mm] = Ab[(k0 + kk + 4) * HW_ + mm];
        Bs[kk][mm]     = g_wpt[(k0 + kk) * O_ + n0 + mm];
        Bs[kk + 4][mm] = g_wpt[(k0 + kk + 4) * O_ + n0 + mm];
        __syncthreads();
#pragma unroll
        for (int kki = 0; kki < 8; ++kki) {
            float4 a4 = *(const float4*)&As[kki][tx * 4];
            float4 b4 = *(const float4*)&Bs[kki][ty * 4];
            acc[0][0] = fmaf(a4.x, b4.x, acc[0][0]);
            acc[1][0] = fmaf(a4.y, b4.x, acc[1][0]);
            acc[2][0] = fmaf(a4.z, b4.x, acc[2][0]);
            acc[3][0] = fmaf(a4.w, b4.x, acc[3][0]);
            acc[0][1] = fmaf(a4.x, b4.y, acc[0][1]);
            acc[1][1] = fmaf(a4.y, b4.y, acc[1][1]);
            acc[2][1] = fmaf(a4.z, b4.y, acc[2][1]);
            acc[3][1] = fmaf(a4.w, b4.y, acc[3][1]);
            acc[0][2] = fmaf(a4.x, b4.z, acc[0][2]);
            acc[1][2] = fmaf(a4.y, b4.z, acc[1][2]);
            acc[2][2] = fmaf(a4.z, b4.z, acc[2][2]);
            acc[3][2] = fmaf(a4.w, b4.z, acc[3][2]);
            acc[0][3] = fmaf(a4.x, b4.w, acc[0][3]);
            acc[1][3] = fmaf(a4.y, b4.w, acc[1][3]);
            acc[2][3] = fmaf(a4.z, b4.w, acc[2][3]);
            acc[3][3] = fmaf(a4.w, b4.w, acc[3][3]);
        }
        __syncthreads();
    }

    float* ob = out + (b * O_ + n0) * HW_ + m0;
#pragma unroll
    for (int o = 0; o < 4; ++o) {
        float btv = __ldg(g_betap + n0 + ty * 4 + o);
        float4 st = make_float4(fmaxf(acc[0][o] + btv, 0.f),
                                fmaxf(acc[1][o] + btv, 0.f),
                                fmaxf(acc[2][o] + btv, 0.f),
                                fmaxf(acc[3][o] + btv, 0.f));
        *(float4*)&ob[(ty * 4 + o) * HW_ + tx * 4] = st;
    }
}

// ---------------- launch ----------------
extern "C" void kernel_launch(void* const* d_in, const int* in_sizes, int n_in,
                              void* d_out, int out_size) {
    const float* x      = (const float*)d_in[0];
    const float* w_off3 = (const float*)d_in[1];
    const float* b_off3 = (const float*)d_in[2];
    const float* w_dw3  = (const float*)d_in[3];
    const float* g3     = (const float*)d_in[4];
    const float* be3    = (const float*)d_in[5];
    const float* m3     = (const float*)d_in[6];
    const float* v3     = (const float*)d_in[7];
    const float* w_off5 = (const float*)d_in[8];
    const float* b_off5 = (const float*)d_in[9];
    const float* w_dw5  = (const float*)d_in[10];
    const float* g5     = (const float*)d_in[11];
    const float* be5    = (const float*)d_in[12];
    const float* m5     = (const float*)d_in[13];
    const float* v5     = (const float*)d_in[14];
    const float* w_off7 = (const float*)d_in[15];
    const float* b_off7 = (const float*)d_in[16];
    const float* w_dw7  = (const float*)d_in[17];
    const float* g7     = (const float*)d_in[18];
    const float* be7    = (const float*)d_in[19];
    const float* m7     = (const float*)d_in[20];
    const float* v7     = (const float*)d_in[21];
    const float* w_pw   = (const float*)d_in[22];
    const float* gp     = (const float*)d_in[23];
    const float* bp     = (const float*)d_in[24];
    const float* mp     = (const float*)d_in[25];
    const float* vp     = (const float*)d_in[26];
    float* out = (float*)d_out;

    // single fused weight-prep launch (3 transposes + pw fold)
    {
        dim3 g((864 * 100 + 255) / 256, 4);   // covers max(86400, 55296) elements
        prep_all_kernel<<<g, 256>>>(w_off3, w_off5, w_off7, w_pw, gp, bp, mp, vp);
    }

    dim3 gHB(H_, B_);
    // offset convs
    offconv_kernel<18, 20, 0><<<gHB, 256>>>(x, b_off3);
    offconv_kernel<50, 52, 1><<<gHB, 256>>>(x, b_off5);
    offconv_kernel<98, 100, 2><<<gHB, 256>>>(x, b_off7);

    // deformable depthwise + BN + ReLU -> g_xc
    deform_kernel<3, 0><<<gHB, 512>>>(x, w_dw3, g3, be3, m3, v3, 0);
    deform_kernel<5, 1><<<gHB, 512>>>(x, w_dw5, g5, be5, m5, v5, 96);
    deform_kernel<7, 2><<<gHB, 512>>>(x, w_dw7, g7, be7, m7, v7, 192);

    // pointwise GEMM + BN + ReLU
    dim3 gPW(HW_ / 64, O_ / 64, B_);
    pwgemm_kernel<<<gPW, 256>>>(out);
}

// round 15
// speedup vs baseline: 1.1393x; 1.1393x over previous
#include <cuda_runtime.h>
#include <cuda_bf16.h>
#include <cstdint>

// Problem constants
#define B_ 4
#define C_ 96
#define H_ 64
#define W_ 64
#define HW_ 4096
#define O_ 192
#define CC_ 288   // 3*C

// ---------------- scratch (device globals; no allocation allowed) ----------------
__device__ __align__(16) float g_off3[B_*18*HW_];
__device__ __align__(16) float g_off5[B_*50*HW_];
__device__ __align__(16) float g_off7[B_*98*HW_];
__device__ __align__(16) float g_xc  [B_*CC_*HW_];
__device__ __align__(16) float g_wt3 [864*20];
__device__ __align__(16) float g_wt5 [864*52];
__device__ __align__(16) float g_wt7 [864*100];
__device__ __align__(16) float g_wpt [CC_*O_];
__device__ __align__(16) float g_betap[O_];

// ---------------- fused weight prep ----------------
__global__ void prep_all_kernel(const float* __restrict__ w3,
                                const float* __restrict__ w5,
                                const float* __restrict__ w7,
                                const float* __restrict__ w_pw,
                                const float* __restrict__ gp, const float* __restrict__ bp,
                                const float* __restrict__ mp, const float* __restrict__ vp) {
    int br = blockIdx.y;
    int i = blockIdx.x * blockDim.x + threadIdx.x;
    if (br == 3) {
        if (i < CC_ * O_) {
            int c = i / O_, o = i - c * O_;
            float inv = gp[o] * rsqrtf(vp[o] + 1e-5f);
            g_wpt[i] = w_pw[o * CC_ + c] * inv;
        }
        if (i < O_) {
            float inv = gp[i] * rsqrtf(vp[i] + 1e-5f);
            g_betap[i] = bp[i] - mp[i] * inv;
        }
        return;
    }
    const float* w = (br == 0) ? w3 : (br == 1) ? w5 : w7;
    float* wt      = (br == 0) ? g_wt3 : (br == 1) ? g_wt5 : g_wt7;
    int OC  = (br == 0) ? 18 : (br == 1) ? 50 : 98;
    int OCP = (br == 0) ? 20 : (br == 1) ? 52 : 100;
    int total = 864 * OCP;
    if (i >= total) return;
    int r = i / OCP, oc = i - r * OCP;
    wt[i] = (oc < OC) ? w[oc * 864 + r] : 0.f;
}

// ---------------- fused offset conv: all 3 branches, oc chunked by 32 ----------------
// grid = (H, B, 7): z=0 -> branch3 [oc 0..32), z=1..2 -> branch5, z=3..6 -> branch7
// block = 128 threads: 16 pixel-groups (x4 px) x 8 oc-groups (x4 oc)
__global__ __launch_bounds__(128) void offconv_fused_kernel(const float* __restrict__ x,
                                                            const float* __restrict__ b3,
                                                            const float* __restrict__ b5,
                                                            const float* __restrict__ b7) {
    int z = blockIdx.z;
    const float* wt; float* out; const float* bias;
    int OCP, OC, oc0;
    if (z == 0)      { wt = g_wt3; out = g_off3; bias = b3; OCP = 20;  OC = 18; oc0 = 0; }
    else if (z <= 2) { wt = g_wt5; out = g_off5; bias = b5; OCP = 52;  OC = 50; oc0 = (z - 1) * 32; }
    else             { wt = g_wt7; out = g_off7; bias = b7; OCP = 100; OC = 98; oc0 = (z - 3) * 32; }

    __shared__ float xs[8][3][72];
    int h = blockIdx.x, b = blockIdx.y;
    int t = threadIdx.x;
    int pg = t & 15;          // pixel group -> 4 pixels
    int og = t >> 4;          // oc group 0..7 -> 4 channels
    int px0 = pg * 4;
    int gi4 = oc0 + og * 4;   // first oc column (padded space)
    bool active = (gi4 < OCP);

    float acc[4][4] = {};     // [pixel][oc]
    const float* xb = x + b * C_ * HW_;

    for (int cc = 0; cc < C_; cc += 8) {
        // stage 8 channels x 3 rows x (W+halo)
        for (int idx = t; idx < 8 * 3 * 72; idx += 128) {
            int ci = idx / 216; int rem = idx - ci * 216;
            int ky = rem / 72;  int s = rem - ky * 72;
            int xcol = s - 1;   int yrow = h - 1 + ky;
            float v = 0.f;
            if (xcol >= 0 && xcol < W_ && yrow >= 0 && yrow < H_)
                v = __ldg(xb + (cc + ci) * HW_ + yrow * W_ + xcol);
            xs[ci][ky][s] = v;
        }
        __syncthreads();

#pragma unroll 4
        for (int ci = 0; ci < 8; ++ci) {
#pragma unroll
            for (int ky = 0; ky < 3; ++ky) {
                float4 va = *(const float4*)&xs[ci][ky][px0];
                float4 vb = *(const float4*)&xs[ci][ky][px0 + 4];
                float v[6] = {va.x, va.y, va.z, va.w, vb.x, vb.y};
                const float* wr = wt + ((cc + ci) * 9 + ky * 3) * OCP + gi4;
                if (active) {
#pragma unroll
                    for (int kx = 0; kx < 3; ++kx) {
                        float4 w4 = __ldg((const float4*)(wr + kx * OCP));
#pragma unroll
                        for (int pp = 0; pp < 4; ++pp) {
                            float xv = v[pp + kx];
                            acc[pp][0] = fmaf(xv, w4.x, acc[pp][0]);
                            acc[pp][1] = fmaf(xv, w4.y, acc[pp][1]);
                            acc[pp][2] = fmaf(xv, w4.z, acc[pp][2]);
                            acc[pp][3] = fmaf(xv, w4.w, acc[pp][3]);
                        }
                    }
                }
            }
        }
        __syncthreads();
    }

    if (active) {
        float* ob = out + b * OC * HW_ + h * W_;
#pragma unroll
        for (int o = 0; o < 4; ++o) {
            int oc = gi4 + o;
            if (oc < OC) {
                float bs = __ldg(bias + oc);
                float4 st = make_float4(acc[0][o] + bs, acc[1][o] + bs,
                                        acc[2][o] + bs, acc[3][o] + bs);
                *(float4*)&ob[oc * HW_ + px0] = st;
            }
        }
    }
}

// ---------------- deformable sample + depthwise + BN + ReLU ----------------
// grid = (H, B, 2): z splits the 96 channels into two 48-channel halves
// block = 512 threads: 64 pixels x 8 channel groups; 2 channels per thread/iter.
template<int K, int BR>
__global__ __launch_bounds__(512) void deform_kernel(const float* __restrict__ x,
                                                     const float* __restrict__ wdw,
                                                     const float* __restrict__ gm,
                                                     const float* __restrict__ bt,
                                                     const float* __restrict__ mn,
                                                     const float* __restrict__ vr,
                                                     int cofs) {
    constexpr int K2 = K * K;
    constexpr int R  = (K - 1) / 2;
    const float* off = (BR == 0) ? g_off3 : (BR == 1) ? g_off5 : g_off7;

    __shared__ int    s_m[K2 * 64];
    __shared__ float2 s_w[K2 * 64];
    __shared__ float  s_dw[C_ * K2];

    int h = blockIdx.x, b = blockIdx.y;
    int zc = blockIdx.z * 48;    // channel-half base
    int t = threadIdx.x;

    for (int idx = t; idx < C_ * K2; idx += 512)
        s_dw[idx] = wdw[idx];

    for (int idx = t; idx < K2 * 64; idx += 512) {
        int j = idx >> 6, p = idx & 63;
        const float* ob = off + ((b * (2 * K2) + j) * H_ + h) * W_;
        float dy = __ldg(ob + p);
        float dx = __ldg(ob + K2 * HW_ + p);
        float py = (float)h + (float)(j / K - R) + dy;
        float px = (float)p + (float)(j % K - R) + dx;
        py = fminf(fmaxf(py, 0.f), (float)(H_ - 1));
        px = fminf(fmaxf(px, 0.f), (float)(W_ - 1));
        float fy = floorf(py), fx = floorf(px);
        int y0 = (int)fy, x0 = (int)fx;
        int xst = (x0 < W_ - 1) ? 1 : 0;
        int yst = (y0 < H_ - 1) ? 1 : 0;
        s_m[idx] = (y0 * W_ + x0) | (xst << 16) | (yst << 17);
        s_w[idx] = make_float2(py - fy, px - fx);
    }
    __syncthreads();

    int p  = t & 63;
    int cg = t >> 6;
    // 48 channels per z-half / (8 groups * 2 per iter) = 3 outer iterations
    for (int c0 = zc; c0 < zc + 48; c0 += 16) {
        int ca = c0 + cg;
        int cb = ca + 8;
        const float* xpa = x + (b * C_ + ca) * HW_;
        const float* xpb = x + (b * C_ + cb) * HW_;
        const float* wra = s_dw + ca * K2;
        const float* wrb = s_dw + cb * K2;
        float acca = 0.f, accb = 0.f;

        if constexpr (K2 <= 25) {
#pragma unroll
            for (int j = 0; j < K2; ++j) {
                int meta = s_m[(j << 6) + p];
                float2 wv = s_w[(j << 6) + p];
                int base = meta & 0xFFFF;
                int xst  = (meta >> 16) & 1;
                int yst  = ((meta >> 17) & 1) ? W_ : 0;
                float a00 = __ldg(xpa + base);
                float a01 = __ldg(xpa + base + xst);
                float a10 = __ldg(xpa + base + yst);
                float a11 = __ldg(xpa + base + yst + xst);
                float b00 = __ldg(xpb + base);
                float b01 = __ldg(xpb + base + xst);
                float b10 = __ldg(xpb + base + yst);
                float b11 = __ldg(xpb + base + yst + xst);
                float ta = a00 + wv.y * (a01 - a00);
                float ua = a10 + wv.y * (a11 - a10);
                float sa = ta + wv.x * (ua - ta);
                float tb = b00 + wv.y * (b01 - b00);
                float ub = b10 + wv.y * (b11 - b10);
                float sb = tb + wv.x * (ub - tb);
                acca = fmaf(sa, wra[j], acca);
                accb = fmaf(sb, wrb[j], accb);
            }
        } else {
#pragma unroll 7
            for (int j = 0; j < K2; ++j) {
                int meta = s_m[(j << 6) + p];
                float2 wv = s_w[(j << 6) + p];
                int base = meta & 0xFFFF;
                int xst  = (meta >> 16) & 1;
                int yst  = ((meta >> 17) & 1) ? W_ : 0;
                float a00 = __ldg(xpa + base);
                float a01 = __ldg(xpa + base + xst);
                float a10 = __ldg(xpa + base + yst);
                float a11 = __ldg(xpa + base + yst + xst);
                float b00 = __ldg(xpb + base);
                float b01 = __ldg(xpb + base + xst);
                float b10 = __ldg(xpb + base + yst);
                float b11 = __ldg(xpb + base + yst + xst);
                float ta = a00 + wv.y * (a01 - a00);
                float ua = a10 + wv.y * (a11 - a10);
                float sa = ta + wv.x * (ua - ta);
                float tb = b00 + wv.y * (b01 - b00);
                float ub = b10 + wv.y * (b11 - b10);
                float sb = tb + wv.x * (ub - tb);
                acca = fmaf(sa, wra[j], acca);
                accb = fmaf(sb, wrb[j], accb);
            }
        }

        float inva = __ldg(gm + ca) * rsqrtf(__ldg(vr + ca) + 1e-5f);
        float invb = __ldg(gm + cb) * rsqrtf(__ldg(vr + cb) + 1e-5f);
        float oa  = fmaf(acca, inva, __ldg(bt + ca) - __ldg(mn + ca) * inva);
        float obv = fmaf(accb, invb, __ldg(bt + cb) - __ldg(mn + cb) * invb);
        g_xc[((b * CC_ + cofs + ca) * H_ + h) * W_ + p] = fmaxf(oa, 0.f);
        g_xc[((b * CC_ + cofs + cb) * H_ + h) * W_ + p] = fmaxf(obv, 0.f);
    }
}

// ---------------- pointwise GEMM (fused BN+ReLU) ----------------
__global__ __launch_bounds__(256) void pwgemm_kernel(float* __restrict__ out) {
    __shared__ float As[8][64];
    __shared__ float Bs[8][64];
    int b  = blockIdx.z;
    int m0 = blockIdx.x * 64;
    int n0 = blockIdx.y * 64;
    int t  = threadIdx.x;
    int tx = t & 15, ty = t >> 4;

    float acc[4][4] = {};
    const float* Ab = g_xc + b * CC_ * HW_ + m0;

    for (int k0 = 0; k0 < CC_; k0 += 8) {
        int kk = t >> 6, mm = t & 63;
        As[kk][mm]     = Ab[(k0 + kk) * HW_ + mm];
        As[kk + 4][mm] = Ab[(k0 + kk + 4) * HW_ + mm];
        Bs[kk][mm]     = g_wpt[(k0 + kk) * O_ + n0 + mm];
        Bs[kk + 4][mm] = g_wpt[(k0 + kk + 4) * O_ + n0 + mm];
        __syncthreads();
#pragma unroll
        for (int kki = 0; kki < 8; ++kki) {
            float4 a4 = *(const float4*)&As[kki][tx * 4];
            float4 b4 = *(const float4*)&Bs[kki][ty * 4];
            acc[0][0] = fmaf(a4.x, b4.x, acc[0][0]);
            acc[1][0] = fmaf(a4.y, b4.x, acc[1][0]);
            acc[2][0] = fmaf(a4.z, b4.x, acc[2][0]);
            acc[3][0] = fmaf(a4.w, b4.x, acc[3][0]);
            acc[0][1] = fmaf(a4.x, b4.y, acc[0][1]);
            acc[1][1] = fmaf(a4.y, b4.y, acc[1][1]);
            acc[2][1] = fmaf(a4.z, b4.y, acc[2][1]);
            acc[3][1] = fmaf(a4.w, b4.y, acc[3][1]);
            acc[0][2] = fmaf(a4.x, b4.z, acc[0][2]);
            acc[1][2] = fmaf(a4.y, b4.z, acc[1][2]);
            acc[2][2] = fmaf(a4.z, b4.z, acc[2][2]);
            acc[3][2] = fmaf(a4.w, b4.z, acc[3][2]);
            acc[0][3] = fmaf(a4.x, b4.w, acc[0][3]);
            acc[1][3] = fmaf(a4.y, b4.w, acc[1][3]);
            acc[2][3] = fmaf(a4.z, b4.w, acc[2][3]);
            acc[3][3] = fmaf(a4.w, b4.w, acc[3][3]);
        }
        __syncthreads();
    }

    float* ob = out + (b * O_ + n0) * HW_ + m0;
#pragma unroll
    for (int o = 0; o < 4; ++o) {
        float btv = __ldg(g_betap + n0 + ty * 4 + o);
        float4 st = make_float4(fmaxf(acc[0][o] + btv, 0.f),
                                fmaxf(acc[1][o] + btv, 0.f),
                                fmaxf(acc[2][o] + btv, 0.f),
                                fmaxf(acc[3][o] + btv, 0.f));
        *(float4*)&ob[(ty * 4 + o) * HW_ + tx * 4] = st;
    }
}

// ---------------- launch ----------------
extern "C" void kernel_launch(void* const* d_in, const int* in_sizes, int n_in,
                              void* d_out, int out_size) {
    const float* x      = (const float*)d_in[0];
    const float* w_off3 = (const float*)d_in[1];
    const float* b_off3 = (const float*)d_in[2];
    const float* w_dw3  = (const float*)d_in[3];
    const float* g3     = (const float*)d_in[4];
    const float* be3    = (const float*)d_in[5];
    const float* m3     = (const float*)d_in[6];
    const float* v3     = (const float*)d_in[7];
    const float* w_off5 = (const float*)d_in[8];
    const float* b_off5 = (const float*)d_in[9];
    const float* w_dw5  = (const float*)d_in[10];
    const float* g5     = (const float*)d_in[11];
    const float* be5    = (const float*)d_in[12];
    const float* m5     = (const float*)d_in[13];
    const float* v5     = (const float*)d_in[14];
    const float* w_off7 = (const float*)d_in[15];
    const float* b_off7 = (const float*)d_in[16];
    const float* w_dw7  = (const float*)d_in[17];
    const float* g7     = (const float*)d_in[18];
    const float* be7    = (const float*)d_in[19];
    const float* m7     = (const float*)d_in[20];
    const float* v7     = (const float*)d_in[21];
    const float* w_pw   = (const float*)d_in[22];
    const float* gp     = (const float*)d_in[23];
    const float* bp     = (const float*)d_in[24];
    const float* mp     = (const float*)d_in[25];
    const float* vp     = (const float*)d_in[26];
    float* out = (float*)d_out;

    // single fused weight-prep launch (3 transposes + pw fold)
    {
        dim3 g((864 * 100 + 255) / 256, 4);
        prep_all_kernel<<<g, 256>>>(w_off3, w_off5, w_off7, w_pw, gp, bp, mp, vp);
    }

    // fused offset convs: all branches + oc-chunks in one launch for occupancy
    {
        dim3 g(H_, B_, 7);
        offconv_fused_kernel<<<g, 128>>>(x, b_off3, b_off5, b_off7);
    }

    // deformable depthwise + BN + ReLU -> g_xc (channel-split for occupancy)
    dim3 gHBZ(H_, B_, 2);
    deform_kernel<3, 0><<<gHBZ, 512>>>(x, w_dw3, g3, be3, m3, v3, 0);
    deform_kernel<5, 1><<<gHBZ, 512>>>(x, w_dw5, g5, be5, m5, v5, 96);
    deform_kernel<7, 2><<<gHBZ, 512>>>(x, w_dw7, g7, be7, m7, v7, 192);

    // pointwise GEMM + BN + ReLU
    dim3 gPW(HW_ / 64, O_ / 64, B_);
    pwgemm_kernel<<<gPW, 256>>>(out);
}